// round 5
// baseline (speedup 1.0000x reference)
#include <cuda_runtime.h>
#include <math.h>

#define NN 50000
#define EE 800000
#define F 32
#define H 64
#define NINVC 128
#define GMAX 2048
#define EPSF 1e-6f
#define TILE 64

// ---------------- scratch (device globals; no allocation) ----------------
__device__ float d_s[NN * F];          // node scalar features
__device__ float d_v[NN * F * 3];      // node vector features [n][f][d]
__device__ float d_as[NN * F];         // scalar message accumulator
__device__ float d_av[NN * F * 3];     // vector message accumulator
__device__ float d_cnt[NN];            // in-degree
__device__ float d_xgsum[GMAX * NINVC];
__device__ float d_gcnt[GMAX];
__device__ float d_xg[GMAX * NINVC];
__device__ float d_z1[GMAX * NINVC];
__device__ float d_m1[NINVC];
__device__ float d_r1[NINVC];
__device__ float d_m2[NINVC];
__device__ float d_r2[NINVC];

__device__ __forceinline__ float elu1(float x) { return x > 0.f ? x : expm1f(x); }

// ---------------- zero accumulators ----------------
__global__ void zero_kernel() {
    int stride = gridDim.x * blockDim.x;
    for (int i = blockIdx.x * blockDim.x + threadIdx.x; i < NN * F * 3; i += stride) {
        d_av[i] = 0.f;
        if (i < NN * F) d_as[i] = 0.f;
        if (i < NN) d_cnt[i] = 0.f;
        if (i < GMAX * NINVC) d_xgsum[i] = 0.f;
        if (i < GMAX) d_gcnt[i] = 0.f;
    }
}

// ---------------- embedding: s = x@W_es + b_es ; v = (x@W_ev) outer pos ----------------
__global__ void embed_kernel(const float* __restrict__ x, const float* __restrict__ pos,
                             const float* __restrict__ Wes, const float* __restrict__ bes,
                             const float* __restrict__ Wev, int Nn) {
    int idx = blockIdx.x * blockDim.x + threadIdx.x;
    if (idx >= Nn * F) return;
    int n = idx / F, f = idx & (F - 1);
    float xs[5];
#pragma unroll
    for (int i = 0; i < 5; i++) xs[i] = x[n * 5 + i];
    float as = bes[f], av = 0.f;
#pragma unroll
    for (int i = 0; i < 5; i++) { as += xs[i] * Wes[i * F + f]; av += xs[i] * Wev[i * F + f]; }
    d_s[idx] = as;
    float px = pos[n * 3], py = pos[n * 3 + 1], pz = pos[n * 3 + 2];
    d_v[idx * 3 + 0] = av * px;
    d_v[idx * 3 + 1] = av * py;
    d_v[idx * 3 + 2] = av * pz;
}

// ---------------- in-degree over dst ----------------
__global__ void degree_kernel(const int* __restrict__ ei, int E) {
    int e = blockIdx.x * blockDim.x + threadIdx.x;
    if (e < E) atomicAdd(&d_cnt[ei[E + e]], 1.f);
}

// ---------------- fused edge MLP + message + scatter (per layer) ----------------
__global__ void __launch_bounds__(256) msg_kernel(
    const float* __restrict__ pos, const int* __restrict__ ei,
    const float* __restrict__ ea,
    const float* __restrict__ W1, const float* __restrict__ b1,
    const float* __restrict__ W2, const float* __restrict__ b2, int E) {
    __shared__ float sW1[5 * H];       // 320
    __shared__ float sb1[H];           // 64
    __shared__ float sW2[H * 3 * F];   // 6144
    __shared__ float sb2[3 * F];       // 96
    __shared__ float sEIn[TILE * 5];
    __shared__ float sU[TILE * 3];
    __shared__ float h1T[H * TILE];    // transposed: [col][edge]
    __shared__ int sSrc[TILE];
    __shared__ int sDst[TILE];

    int tid = threadIdx.x;
    for (int i = tid; i < 5 * H; i += 256) sW1[i] = W1[i];
    if (tid < H) sb1[tid] = b1[tid];
    for (int i = tid; i < H * 3 * F; i += 256) sW2[i] = W2[i];
    if (tid < 3 * F) sb2[tid] = b2[tid];

    int ntiles = (E + TILE - 1) / TILE;
    for (int t = blockIdx.x; t < ntiles; t += gridDim.x) {
        int e0 = t * TILE;
        __syncthreads();  // protect shared reuse + weight-load visibility
        if (tid < TILE) {
            int e = e0 + tid;
            if (e < E) {
                int sn = ei[e], dn = ei[E + e];
                sSrc[tid] = sn; sDst[tid] = dn;
                float dx = pos[dn * 3 + 0] - pos[sn * 3 + 0];
                float dy = pos[dn * 3 + 1] - pos[sn * 3 + 1];
                float dz = pos[dn * 3 + 2] - pos[sn * 3 + 2];
                float dist = sqrtf(dx * dx + dy * dy + dz * dz + EPSF);
                sEIn[tid * 5 + 0] = dist;
                sEIn[tid * 5 + 1] = ea[e * 4 + 0];
                sEIn[tid * 5 + 2] = ea[e * 4 + 1];
                sEIn[tid * 5 + 3] = ea[e * 4 + 2];
                sEIn[tid * 5 + 4] = ea[e * 4 + 3];
                float inv = 1.f / dist;
                sU[tid * 3 + 0] = dx * inv;
                sU[tid * 3 + 1] = dy * inv;
                sU[tid * 3 + 2] = dz * inv;
            } else {
                sSrc[tid] = 0; sDst[tid] = 0;
#pragma unroll
                for (int i = 0; i < 5; i++) sEIn[tid * 5 + i] = 0.f;
#pragma unroll
                for (int i = 0; i < 3; i++) sU[tid * 3 + i] = 0.f;
            }
        }
        __syncthreads();

        // GEMM1: h1T[c][e] = elu(b1[c] + edge_in[e] . W1[:,c])
        {
            int e = tid & (TILE - 1);
            int ch = tid >> 6;  // 0..3 -> 16 cols each
            float ein[5];
#pragma unroll
            for (int i = 0; i < 5; i++) ein[i] = sEIn[e * 5 + i];
#pragma unroll
            for (int cc = 0; cc < 16; cc++) {
                int c = ch * 16 + cc;
                float a = sb1[c];
#pragma unroll
                for (int i = 0; i < 5; i++) a += ein[i] * sW1[i * H + c];
                h1T[c * TILE + e] = elu1(a);
            }
        }
        __syncthreads();

        // GEMM2 (64 -> 96) with register tile: 2 edges x 4 f x {gs,gv,gsv}
        int og = tid >> 5;  // 0..7 -> f = og*4 + j
        int eg = tid & 31;  // 0..31 -> edges 2*eg, 2*eg+1
        float aS[2][4] = {}, aV[2][4] = {}, aX[2][4] = {};
#pragma unroll 4
        for (int k = 0; k < H; k++) {
            float2 hh = *(const float2*)&h1T[k * TILE + eg * 2];
            float4 ws = *(const float4*)&sW2[k * 3 * F + og * 4];
            float4 wv = *(const float4*)&sW2[k * 3 * F + F + og * 4];
            float4 wx = *(const float4*)&sW2[k * 3 * F + 2 * F + og * 4];
            float wsA[4] = {ws.x, ws.y, ws.z, ws.w};
            float wvA[4] = {wv.x, wv.y, wv.z, wv.w};
            float wxA[4] = {wx.x, wx.y, wx.z, wx.w};
#pragma unroll
            for (int j = 0; j < 4; j++) {
                aS[0][j] += hh.x * wsA[j];  aS[1][j] += hh.y * wsA[j];
                aV[0][j] += hh.x * wvA[j];  aV[1][j] += hh.y * wvA[j];
                aX[0][j] += hh.x * wxA[j];  aX[1][j] += hh.y * wxA[j];
            }
        }

        // messages + scatter
#pragma unroll
        for (int i = 0; i < 2; i++) {
            int e = eg * 2 + i;
            if (e0 + e >= E) continue;
            int sn = sSrc[e], dn = sDst[e];
            float ux = sU[e * 3], uy = sU[e * 3 + 1], uz = sU[e * 3 + 2];
#pragma unroll
            for (int j = 0; j < 4; j++) {
                int f = og * 4 + j;
                float gs = aS[i][j] + sb2[f];
                float gv = aV[i][j] + sb2[F + f];
                float gx = aX[i][j] + sb2[2 * F + f];
                float sv = d_s[sn * F + f];
                atomicAdd(&d_as[dn * F + f], gs * sv);
                float c = gx * sv;
                const float* vp = &d_v[sn * F * 3 + f * 3];
                atomicAdd(&d_av[dn * F * 3 + f * 3 + 0], gv * vp[0] + c * ux);
                atomicAdd(&d_av[dn * F * 3 + f * 3 + 1], gv * vp[1] + c * uy);
                atomicAdd(&d_av[dn * F * 3 + f * 3 + 2], gv * vp[2] + c * uz);
            }
        }
    }
}

// ---------------- node update: s += elu(as@Ws); v += av@Wv ----------------
__global__ void __launch_bounds__(256) upd_kernel(const float* __restrict__ Ws,
                                                  const float* __restrict__ Wv, int Nn) {
    __shared__ float sWs[F * F], sWv[F * F];
    __shared__ float sAs[8][F];
    __shared__ float sAv[8][F][3];
    int tid = threadIdx.x;
    for (int i = tid; i < F * F; i += 256) { sWs[i] = Ws[i]; sWv[i] = Wv[i]; }
    int ln = tid >> 5, f = tid & 31;
    int n = blockIdx.x * 8 + ln;
    bool ok = n < Nn;
    if (ok) {
        float inv = 1.f / fmaxf(d_cnt[n], 1.f);
        sAs[ln][f] = d_as[n * F + f] * inv;
        d_as[n * F + f] = 0.f;  // ready for next layer
#pragma unroll
        for (int d = 0; d < 3; d++) {
            sAv[ln][f][d] = d_av[n * F * 3 + f * 3 + d] * inv;
            d_av[n * F * 3 + f * 3 + d] = 0.f;
        }
    }
    __syncthreads();
    if (ok) {
        float a = 0, vx = 0, vy = 0, vz = 0;
#pragma unroll
        for (int g = 0; g < F; g++) {
            float w1 = sWs[g * F + f], w2 = sWv[g * F + f];
            a  += sAs[ln][g] * w1;
            vx += sAv[ln][g][0] * w2;
            vy += sAv[ln][g][1] * w2;
            vz += sAv[ln][g][2] * w2;
        }
        d_s[n * F + f] += elu1(a);
        d_v[n * F * 3 + f * 3 + 0] += vx;
        d_v[n * F * 3 + f * 3 + 1] += vy;
        d_v[n * F * 3 + f * 3 + 2] += vz;
    }
}

// ---------------- graph node counts ----------------
__global__ void gcnt_kernel(const int* __restrict__ batch, int Nn) {
    int n = blockIdx.x * blockDim.x + threadIdx.x;
    if (n < Nn) atomicAdd(&d_gcnt[batch[n]], 1.f);
}

// ---------------- invariant map + graph-sum pooling ----------------
__global__ void __launch_bounds__(128) inv_kernel(const int* __restrict__ batch,
                                                  const float* __restrict__ Winv,
                                                  const float* __restrict__ binv, int Nn) {
    __shared__ float sW[2 * F * NINVC];  // 64*128*4 = 32KB
    __shared__ float sFeat[2 * F];
    int tid = threadIdx.x;
    for (int i = tid; i < 2 * F * NINVC; i += 128) sW[i] = Winv[i];
    float bj = binv[tid];
    int n0 = blockIdx.x * 32;
    for (int nn = 0; nn < 32; nn++) {
        int n = n0 + nn;
        if (n >= Nn) break;
        __syncthreads();
        if (tid < F) sFeat[tid] = d_s[n * F + tid];
        else if (tid < 2 * F) {
            int f = tid - F;
            float a = d_v[n * F * 3 + f * 3 + 0];
            float b = d_v[n * F * 3 + f * 3 + 1];
            float c = d_v[n * F * 3 + f * 3 + 2];
            sFeat[tid] = sqrtf(a * a + b * b + c * c + EPSF);
        }
        __syncthreads();
        float acc = bj;
#pragma unroll 8
        for (int i = 0; i < 2 * F; i++) acc += sFeat[i] * sW[i * NINVC + tid];
        atomicAdd(&d_xgsum[batch[n] * NINVC + tid], acc);
    }
}

// ---------------- mean pool finalize ----------------
__global__ void poolfin_kernel(int G) {
    int i = blockIdx.x * blockDim.x + threadIdx.x;
    if (i < G * NINVC) d_xg[i] = d_xgsum[i] / fmaxf(d_gcnt[i / NINVC], 1.f);
}

// ---------------- batchnorm column stats ----------------
__global__ void bnstats_kernel(int which, int G) {
    const float* z = which ? d_z1 : d_xg;
    float* mean = which ? d_m2 : d_m1;
    float* rstd = which ? d_r2 : d_r1;
    int j = blockIdx.x;
    __shared__ float sS[256], sQ[256];
    float s = 0.f, q = 0.f;
    for (int g = threadIdx.x; g < G; g += 256) {
        float val = z[g * NINVC + j];
        s += val; q += val * val;
    }
    sS[threadIdx.x] = s; sQ[threadIdx.x] = q;
    __syncthreads();
    for (int off = 128; off > 0; off >>= 1) {
        if (threadIdx.x < off) { sS[threadIdx.x] += sS[threadIdx.x + off]; sQ[threadIdx.x] += sQ[threadIdx.x + off]; }
        __syncthreads();
    }
    if (threadIdx.x == 0) {
        float m = sS[0] / (float)G;
        float var = sQ[0] / (float)G - m * m;
        mean[j] = m;
        rstd[j] = rsqrtf(var + 1e-5f);
    }
}

// ---------------- fc1: z1 = elu(bn(xg)) @ Wf1 + bf1 ----------------
__global__ void __launch_bounds__(128) fc1_kernel(const float* __restrict__ Wf1,
                                                  const float* __restrict__ bf1,
                                                  const float* __restrict__ g1,
                                                  const float* __restrict__ be1, int G) {
    __shared__ float sA[NINVC];
    int tid = threadIdx.x;
    float gj = g1[tid], bej = be1[tid], mj = d_m1[tid], rj = d_r1[tid], bfj = bf1[tid];
    int r0 = blockIdx.x * 16;
    for (int rr = 0; rr < 16; rr++) {
        int r = r0 + rr;
        if (r >= G) break;
        __syncthreads();
        float a = (d_xg[r * NINVC + tid] - mj) * rj * gj + bej;
        sA[tid] = elu1(a);
        __syncthreads();
        float acc = bfj;
#pragma unroll 8
        for (int i = 0; i < NINVC; i++) acc += sA[i] * Wf1[i * NINVC + tid];
        d_z1[r * NINVC + tid] = acc;
    }
}

// ---------------- fc2: z = elu(bn(z1)) @ Wf2 + bf2 ----------------
__global__ void fc2_kernel(const float* __restrict__ Wf2, const float* __restrict__ bf2,
                           const float* __restrict__ g2, const float* __restrict__ be2,
                           float* __restrict__ out, int G) {
    int warp = threadIdx.x >> 5, lane = threadIdx.x & 31;
    int r = blockIdx.x * 8 + warp;
    if (r >= G) return;
    float acc = 0.f;
    for (int j = lane; j < NINVC; j += 32) {
        float a = (d_z1[r * NINVC + j] - d_m2[j]) * d_r2[j] * g2[j] + be2[j];
        acc += elu1(a) * Wf2[j];
    }
#pragma unroll
    for (int off = 16; off > 0; off >>= 1) acc += __shfl_down_sync(0xffffffffu, acc, off);
    if (lane == 0) out[r] = acc + bf2[0];
}

// ---------------- launch ----------------
extern "C" void kernel_launch(void* const* d_in, const int* in_sizes, int n_in,
                              void* d_out, int out_size) {
    const float* x     = (const float*)d_in[0];
    const float* pos   = (const float*)d_in[1];
    const int*   ei    = (const int*)d_in[2];    // JAX default x64-disabled -> int32
    const float* ea    = (const float*)d_in[3];
    const int*   batch = (const int*)d_in[4];
    const float* Wes   = (const float*)d_in[5];
    const float* bes   = (const float*)d_in[6];
    const float* Wev   = (const float*)d_in[7];
    const float* W1    = (const float*)d_in[8];
    const float* b1    = (const float*)d_in[9];
    const float* W2    = (const float*)d_in[10];
    const float* b2    = (const float*)d_in[11];
    const float* Ws    = (const float*)d_in[12];
    const float* Wv    = (const float*)d_in[13];
    const float* Winv  = (const float*)d_in[14];
    const float* binv  = (const float*)d_in[15];
    const float* g1    = (const float*)d_in[16];
    const float* be1   = (const float*)d_in[17];
    const float* Wf1   = (const float*)d_in[18];
    const float* bf1   = (const float*)d_in[19];
    const float* g2    = (const float*)d_in[20];
    const float* be2   = (const float*)d_in[21];
    const float* Wf2   = (const float*)d_in[22];
    const float* bf2   = (const float*)d_in[23];

    int Nn = in_sizes[0] / 5;
    int E  = in_sizes[2] / 2;
    int G  = out_size;
    float* out = (float*)d_out;

    zero_kernel<<<2048, 256>>>();
    embed_kernel<<<(Nn * F + 255) / 256, 256>>>(x, pos, Wes, bes, Wev, Nn);
    degree_kernel<<<(E + 255) / 256, 256>>>(ei, E);

    for (int l = 0; l < 4; l++) {
        msg_kernel<<<1480, 256>>>(pos, ei, ea,
                                  W1 + l * 5 * H, b1 + l * H,
                                  W2 + l * H * 3 * F, b2 + l * 3 * F, E);
        upd_kernel<<<(Nn + 7) / 8, 256>>>(Ws + l * F * F, Wv + l * F * F, Nn);
    }

    gcnt_kernel<<<(Nn + 255) / 256, 256>>>(batch, Nn);
    inv_kernel<<<(Nn + 31) / 32, 128>>>(batch, Winv, binv, Nn);
    poolfin_kernel<<<(G * NINVC + 255) / 256, 256>>>(G);
    bnstats_kernel<<<NINVC, 256>>>(0, G);
    fc1_kernel<<<(G + 15) / 16, 128>>>(Wf1, bf1, g1, be1, G);
    bnstats_kernel<<<NINVC, 256>>>(1, G);
    fc2_kernel<<<(G + 7) / 8, 256>>>(Wf2, bf2, g2, be2, out, G);
}

// round 6
// speedup vs baseline: 2.1173x; 2.1173x over previous
#include <cuda_runtime.h>
#include <math.h>

#define NN 50000
#define EE 800000
#define F 32
#define H 64
#define NINVC 128
#define GMAX 2048
#define EPSF 1e-6f
#define TILE 64

// ---------------- scratch (device globals; no allocation) ----------------
// packed node state: {s, vx, vy, vz} per (node, f)
__device__ float4 d_sv[NN * F];
// packed accumulator: {as, avx, avy, avz} per (node, f)
__device__ float4 d_acc[NN * F];
__device__ float d_cnt[NN];            // in-degree
__device__ float d_xgsum[GMAX * NINVC];
__device__ float d_gcnt[GMAX];
__device__ float d_xg[GMAX * NINVC];
__device__ float d_z1[GMAX * NINVC];
__device__ float d_m1[NINVC];
__device__ float d_r1[NINVC];
__device__ float d_m2[NINVC];
__device__ float d_r2[NINVC];

__device__ __forceinline__ float elu1(float x) { return x > 0.f ? x : expm1f(x); }

__device__ __forceinline__ void red_add_v4(float4* addr, float a, float b, float c, float d) {
    asm volatile("red.global.add.v4.f32 [%0], {%1, %2, %3, %4};"
                 :: "l"(addr), "f"(a), "f"(b), "f"(c), "f"(d) : "memory");
}

// ---------------- zero accumulators ----------------
__global__ void zero_kernel() {
    int stride = gridDim.x * blockDim.x;
    float4 z4 = make_float4(0.f, 0.f, 0.f, 0.f);
    for (int i = blockIdx.x * blockDim.x + threadIdx.x; i < NN * F; i += stride) {
        d_acc[i] = z4;
        if (i < NN) d_cnt[i] = 0.f;
        if (i < GMAX * NINVC) d_xgsum[i] = 0.f;
        if (i < GMAX) d_gcnt[i] = 0.f;
    }
}

// ---------------- embedding: s = x@W_es + b_es ; v = (x@W_ev) outer pos ----------------
__global__ void embed_kernel(const float* __restrict__ x, const float* __restrict__ pos,
                             const float* __restrict__ Wes, const float* __restrict__ bes,
                             const float* __restrict__ Wev, int Nn) {
    int idx = blockIdx.x * blockDim.x + threadIdx.x;
    if (idx >= Nn * F) return;
    int n = idx / F, f = idx & (F - 1);
    float xs[5];
#pragma unroll
    for (int i = 0; i < 5; i++) xs[i] = x[n * 5 + i];
    float as = bes[f], av = 0.f;
#pragma unroll
    for (int i = 0; i < 5; i++) { as += xs[i] * Wes[i * F + f]; av += xs[i] * Wev[i * F + f]; }
    float px = pos[n * 3], py = pos[n * 3 + 1], pz = pos[n * 3 + 2];
    d_sv[idx] = make_float4(as, av * px, av * py, av * pz);
}

// ---------------- in-degree over dst ----------------
__global__ void degree_kernel(const int* __restrict__ ei, int E) {
    int e = blockIdx.x * blockDim.x + threadIdx.x;
    if (e < E) atomicAdd(&d_cnt[ei[E + e]], 1.f);
}

// ---------------- fused edge MLP + message + scatter (per layer) ----------------
__global__ void __launch_bounds__(256) msg_kernel(
    const float* __restrict__ pos, const int* __restrict__ ei,
    const float* __restrict__ ea,
    const float* __restrict__ W1, const float* __restrict__ b1,
    const float* __restrict__ W2, const float* __restrict__ b2, int E) {
    __shared__ float sW1[5 * H];       // 320
    __shared__ float sb1[H];           // 64
    __shared__ float sW2[H * 3 * F];   // 6144
    __shared__ float sb2[3 * F];       // 96
    __shared__ float sEIn[TILE * 5];
    __shared__ float sU[TILE * 3];
    __shared__ float h1T[H * TILE];    // transposed: [col][edge]
    __shared__ int sSrc[TILE];
    __shared__ int sDst[TILE];

    int tid = threadIdx.x;
    for (int i = tid; i < 5 * H; i += 256) sW1[i] = W1[i];
    if (tid < H) sb1[tid] = b1[tid];
    for (int i = tid; i < H * 3 * F; i += 256) sW2[i] = W2[i];
    if (tid < 3 * F) sb2[tid] = b2[tid];

    int ntiles = (E + TILE - 1) / TILE;
    for (int t = blockIdx.x; t < ntiles; t += gridDim.x) {
        int e0 = t * TILE;
        __syncthreads();  // protect shared reuse + weight-load visibility
        if (tid < TILE) {
            int e = e0 + tid;
            if (e < E) {
                int sn = ei[e], dn = ei[E + e];
                sSrc[tid] = sn; sDst[tid] = dn;
                float dx = pos[dn * 3 + 0] - pos[sn * 3 + 0];
                float dy = pos[dn * 3 + 1] - pos[sn * 3 + 1];
                float dz = pos[dn * 3 + 2] - pos[sn * 3 + 2];
                float dist = sqrtf(dx * dx + dy * dy + dz * dz + EPSF);
                sEIn[tid * 5 + 0] = dist;
                sEIn[tid * 5 + 1] = ea[e * 4 + 0];
                sEIn[tid * 5 + 2] = ea[e * 4 + 1];
                sEIn[tid * 5 + 3] = ea[e * 4 + 2];
                sEIn[tid * 5 + 4] = ea[e * 4 + 3];
                float inv = 1.f / dist;
                sU[tid * 3 + 0] = dx * inv;
                sU[tid * 3 + 1] = dy * inv;
                sU[tid * 3 + 2] = dz * inv;
            } else {
                sSrc[tid] = 0; sDst[tid] = 0;
#pragma unroll
                for (int i = 0; i < 5; i++) sEIn[tid * 5 + i] = 0.f;
#pragma unroll
                for (int i = 0; i < 3; i++) sU[tid * 3 + i] = 0.f;
            }
        }
        __syncthreads();

        // GEMM1: h1T[c][e] = elu(b1[c] + edge_in[e] . W1[:,c])
        {
            int e = tid & (TILE - 1);
            int ch = tid >> 6;  // 0..3 -> 16 cols each
            float ein[5];
#pragma unroll
            for (int i = 0; i < 5; i++) ein[i] = sEIn[e * 5 + i];
#pragma unroll
            for (int cc = 0; cc < 16; cc++) {
                int c = ch * 16 + cc;
                float a = sb1[c];
#pragma unroll
                for (int i = 0; i < 5; i++) a += ein[i] * sW1[i * H + c];
                h1T[c * TILE + e] = elu1(a);
            }
        }
        __syncthreads();

        // GEMM2 (64 -> 96) with register tile: 2 edges x 4 f x {gs,gv,gsv}
        int og = tid >> 5;  // 0..7 -> f = og*4 + j
        int eg = tid & 31;  // 0..31 -> edges 2*eg, 2*eg+1
        float aS[2][4] = {}, aV[2][4] = {}, aX[2][4] = {};
#pragma unroll 4
        for (int k = 0; k < H; k++) {
            float2 hh = *(const float2*)&h1T[k * TILE + eg * 2];
            float4 ws = *(const float4*)&sW2[k * 3 * F + og * 4];
            float4 wv = *(const float4*)&sW2[k * 3 * F + F + og * 4];
            float4 wx = *(const float4*)&sW2[k * 3 * F + 2 * F + og * 4];
            float wsA[4] = {ws.x, ws.y, ws.z, ws.w};
            float wvA[4] = {wv.x, wv.y, wv.z, wv.w};
            float wxA[4] = {wx.x, wx.y, wx.z, wx.w};
#pragma unroll
            for (int j = 0; j < 4; j++) {
                aS[0][j] += hh.x * wsA[j];  aS[1][j] += hh.y * wsA[j];
                aV[0][j] += hh.x * wvA[j];  aV[1][j] += hh.y * wvA[j];
                aX[0][j] += hh.x * wxA[j];  aX[1][j] += hh.y * wxA[j];
            }
        }

        // messages + scatter: one 16B gather + one 16B vector reduction per (edge,f)
#pragma unroll
        for (int i = 0; i < 2; i++) {
            int e = eg * 2 + i;
            if (e0 + e >= E) continue;
            int sn = sSrc[e], dn = sDst[e];
            float ux = sU[e * 3], uy = sU[e * 3 + 1], uz = sU[e * 3 + 2];
#pragma unroll
            for (int j = 0; j < 4; j++) {
                int f = og * 4 + j;
                float gs = aS[i][j] + sb2[f];
                float gv = aV[i][j] + sb2[F + f];
                float gx = aX[i][j] + sb2[2 * F + f];
                float4 sv = d_sv[sn * F + f];
                float c = gx * sv.x;
                red_add_v4(&d_acc[dn * F + f],
                           gs * sv.x,
                           gv * sv.y + c * ux,
                           gv * sv.z + c * uy,
                           gv * sv.w + c * uz);
            }
        }
    }
}

// ---------------- node update: s += elu(as@Ws); v += av@Wv ----------------
__global__ void __launch_bounds__(256) upd_kernel(const float* __restrict__ Ws,
                                                  const float* __restrict__ Wv, int Nn) {
    __shared__ float sWs[F * F], sWv[F * F];
    __shared__ float4 sA[8][F];
    int tid = threadIdx.x;
    for (int i = tid; i < F * F; i += 256) { sWs[i] = Ws[i]; sWv[i] = Wv[i]; }
    int ln = tid >> 5, f = tid & 31;
    int n = blockIdx.x * 8 + ln;
    bool ok = n < Nn;
    if (ok) {
        float inv = 1.f / fmaxf(d_cnt[n], 1.f);
        float4 a = d_acc[n * F + f];
        sA[ln][f] = make_float4(a.x * inv, a.y * inv, a.z * inv, a.w * inv);
        d_acc[n * F + f] = make_float4(0.f, 0.f, 0.f, 0.f);  // ready for next layer
    }
    __syncthreads();
    if (ok) {
        float a = 0, vx = 0, vy = 0, vz = 0;
#pragma unroll
        for (int g = 0; g < F; g++) {
            float w1 = sWs[g * F + f], w2 = sWv[g * F + f];
            float4 ag = sA[ln][g];
            a  += ag.x * w1;
            vx += ag.y * w2;
            vy += ag.z * w2;
            vz += ag.w * w2;
        }
        float4 cur = d_sv[n * F + f];
        cur.x += elu1(a);
        cur.y += vx;
        cur.z += vy;
        cur.w += vz;
        d_sv[n * F + f] = cur;
    }
}

// ---------------- graph node counts ----------------
__global__ void gcnt_kernel(const int* __restrict__ batch, int Nn) {
    int n = blockIdx.x * blockDim.x + threadIdx.x;
    if (n < Nn) atomicAdd(&d_gcnt[batch[n]], 1.f);
}

// ---------------- invariant map + graph-sum pooling ----------------
__global__ void __launch_bounds__(128) inv_kernel(const int* __restrict__ batch,
                                                  const float* __restrict__ Winv,
                                                  const float* __restrict__ binv, int Nn) {
    __shared__ float sW[2 * F * NINVC];  // 64*128*4 = 32KB
    __shared__ float sFeat[2 * F];
    int tid = threadIdx.x;
    for (int i = tid; i < 2 * F * NINVC; i += 128) sW[i] = Winv[i];
    float bj = binv[tid];
    int n0 = blockIdx.x * 32;
    for (int nn = 0; nn < 32; nn++) {
        int n = n0 + nn;
        if (n >= Nn) break;
        __syncthreads();
        if (tid < F) {
            float4 sv = d_sv[n * F + tid];
            sFeat[tid] = sv.x;
            sFeat[F + tid] = sqrtf(sv.y * sv.y + sv.z * sv.z + sv.w * sv.w + EPSF);
        }
        __syncthreads();
        float acc = bj;
#pragma unroll 8
        for (int i = 0; i < 2 * F; i++) acc += sFeat[i] * sW[i * NINVC + tid];
        atomicAdd(&d_xgsum[batch[n] * NINVC + tid], acc);
    }
}

// ---------------- mean pool finalize ----------------
__global__ void poolfin_kernel(int G) {
    int i = blockIdx.x * blockDim.x + threadIdx.x;
    if (i < G * NINVC) d_xg[i] = d_xgsum[i] / fmaxf(d_gcnt[i / NINVC], 1.f);
}

// ---------------- batchnorm column stats ----------------
__global__ void bnstats_kernel(int which, int G) {
    const float* z = which ? d_z1 : d_xg;
    float* mean = which ? d_m2 : d_m1;
    float* rstd = which ? d_r2 : d_r1;
    int j = blockIdx.x;
    __shared__ float sS[256], sQ[256];
    float s = 0.f, q = 0.f;
    for (int g = threadIdx.x; g < G; g += 256) {
        float val = z[g * NINVC + j];
        s += val; q += val * val;
    }
    sS[threadIdx.x] = s; sQ[threadIdx.x] = q;
    __syncthreads();
    for (int off = 128; off > 0; off >>= 1) {
        if (threadIdx.x < off) { sS[threadIdx.x] += sS[threadIdx.x + off]; sQ[threadIdx.x] += sQ[threadIdx.x + off]; }
        __syncthreads();
    }
    if (threadIdx.x == 0) {
        float m = sS[0] / (float)G;
        float var = sQ[0] / (float)G - m * m;
        mean[j] = m;
        rstd[j] = rsqrtf(var + 1e-5f);
    }
}

// ---------------- fc1: z1 = elu(bn(xg)) @ Wf1 + bf1 ----------------
__global__ void __launch_bounds__(128) fc1_kernel(const float* __restrict__ Wf1,
                                                  const float* __restrict__ bf1,
                                                  const float* __restrict__ g1,
                                                  const float* __restrict__ be1, int G) {
    __shared__ float sA[NINVC];
    int tid = threadIdx.x;
    float gj = g1[tid], bej = be1[tid], mj = d_m1[tid], rj = d_r1[tid], bfj = bf1[tid];
    int r0 = blockIdx.x * 16;
    for (int rr = 0; rr < 16; rr++) {
        int r = r0 + rr;
        if (r >= G) break;
        __syncthreads();
        float a = (d_xg[r * NINVC + tid] - mj) * rj * gj + bej;
        sA[tid] = elu1(a);
        __syncthreads();
        float acc = bfj;
#pragma unroll 8
        for (int i = 0; i < NINVC; i++) acc += sA[i] * Wf1[i * NINVC + tid];
        d_z1[r * NINVC + tid] = acc;
    }
}

// ---------------- fc2: z = elu(bn(z1)) @ Wf2 + bf2 ----------------
__global__ void fc2_kernel(const float* __restrict__ Wf2, const float* __restrict__ bf2,
                           const float* __restrict__ g2, const float* __restrict__ be2,
                           float* __restrict__ out, int G) {
    int warp = threadIdx.x >> 5, lane = threadIdx.x & 31;
    int r = blockIdx.x * 8 + warp;
    if (r >= G) return;
    float acc = 0.f;
    for (int j = lane; j < NINVC; j += 32) {
        float a = (d_z1[r * NINVC + j] - d_m2[j]) * d_r2[j] * g2[j] + be2[j];
        acc += elu1(a) * Wf2[j];
    }
#pragma unroll
    for (int off = 16; off > 0; off >>= 1) acc += __shfl_down_sync(0xffffffffu, acc, off);
    if (lane == 0) out[r] = acc + bf2[0];
}

// ---------------- launch ----------------
extern "C" void kernel_launch(void* const* d_in, const int* in_sizes, int n_in,
                              void* d_out, int out_size) {
    const float* x     = (const float*)d_in[0];
    const float* pos   = (const float*)d_in[1];
    const int*   ei    = (const int*)d_in[2];    // JAX default x64-disabled -> int32
    const float* ea    = (const float*)d_in[3];
    const int*   batch = (const int*)d_in[4];
    const float* Wes   = (const float*)d_in[5];
    const float* bes   = (const float*)d_in[6];
    const float* Wev   = (const float*)d_in[7];
    const float* W1    = (const float*)d_in[8];
    const float* b1    = (const float*)d_in[9];
    const float* W2    = (const float*)d_in[10];
    const float* b2    = (const float*)d_in[11];
    const float* Ws    = (const float*)d_in[12];
    const float* Wv    = (const float*)d_in[13];
    const float* Winv  = (const float*)d_in[14];
    const float* binv  = (const float*)d_in[15];
    const float* g1    = (const float*)d_in[16];
    const float* be1   = (const float*)d_in[17];
    const float* Wf1   = (const float*)d_in[18];
    const float* bf1   = (const float*)d_in[19];
    const float* g2    = (const float*)d_in[20];
    const float* be2   = (const float*)d_in[21];
    const float* Wf2   = (const float*)d_in[22];
    const float* bf2   = (const float*)d_in[23];

    int Nn = in_sizes[0] / 5;
    int E  = in_sizes[2] / 2;
    int G  = out_size;
    float* out = (float*)d_out;

    zero_kernel<<<2048, 256>>>();
    embed_kernel<<<(Nn * F + 255) / 256, 256>>>(x, pos, Wes, bes, Wev, Nn);
    degree_kernel<<<(E + 255) / 256, 256>>>(ei, E);

    for (int l = 0; l < 4; l++) {
        msg_kernel<<<1480, 256>>>(pos, ei, ea,
                                  W1 + l * 5 * H, b1 + l * H,
                                  W2 + l * H * 3 * F, b2 + l * 3 * F, E);
        upd_kernel<<<(Nn + 7) / 8, 256>>>(Ws + l * F * F, Wv + l * F * F, Nn);
    }

    gcnt_kernel<<<(Nn + 255) / 256, 256>>>(batch, Nn);
    inv_kernel<<<(Nn + 31) / 32, 128>>>(batch, Winv, binv, Nn);
    poolfin_kernel<<<(G * NINVC + 255) / 256, 256>>>(G);
    bnstats_kernel<<<NINVC, 256>>>(0, G);
    fc1_kernel<<<(G + 15) / 16, 128>>>(Wf1, bf1, g1, be1, G);
    bnstats_kernel<<<NINVC, 256>>>(1, G);
    fc2_kernel<<<(G + 7) / 8, 256>>>(Wf2, bf2, g2, be2, out, G);
}

// round 8
// speedup vs baseline: 3.1216x; 1.4743x over previous
#include <cuda_runtime.h>
#include <math.h>

#define NN 50000
#define EE 800000
#define F 32
#define H 64
#define NINVC 128
#define GMAX 2048
#define EPSF 1e-6f
#define TILE 64

// ---------------- scratch (device globals; no allocation) ----------------
__device__ float4 d_sv[NN * F];    // packed node state {s, vx, vy, vz}
__device__ float4 d_acc[NN * F];   // packed accumulator {as, avx, avy, avz}
__device__ float d_cnt[NN];
__device__ float d_xgsum[GMAX * NINVC];
__device__ float d_gcnt[GMAX];
__device__ float d_xg[GMAX * NINVC];
__device__ float d_z1[GMAX * NINVC];
__device__ float d_m1[NINVC];
__device__ float d_r1[NINVC];
__device__ float d_m2[NINVC];
__device__ float d_r2[NINVC];

__device__ __forceinline__ float elu1(float x) { return x > 0.f ? x : expm1f(x); }

__device__ __forceinline__ void red_add_v4(float4* addr, float a, float b, float c, float d) {
    asm volatile("red.global.add.v4.f32 [%0], {%1, %2, %3, %4};"
                 :: "l"(addr), "f"(a), "f"(b), "f"(c), "f"(d) : "memory");
}

#define FMA2(acc, a, b) \
    asm("fma.rn.f32x2 %0, %1, %2, %0;" : "+l"(acc) : "l"(a), "l"(b))

#define PACK2(out, v) \
    asm("mov.b64 %0, {%1, %1};" : "=l"(out) : "r"(__float_as_uint(v)))

// ---------------- zero accumulators ----------------
__global__ void zero_kernel() {
    int stride = gridDim.x * blockDim.x;
    float4 z4 = make_float4(0.f, 0.f, 0.f, 0.f);
    for (int i = blockIdx.x * blockDim.x + threadIdx.x; i < NN * F; i += stride) {
        d_acc[i] = z4;
        if (i < NN) d_cnt[i] = 0.f;
        if (i < GMAX * NINVC) d_xgsum[i] = 0.f;
        if (i < GMAX) d_gcnt[i] = 0.f;
    }
}

// ---------------- embedding ----------------
__global__ void embed_kernel(const float* __restrict__ x, const float* __restrict__ pos,
                             const float* __restrict__ Wes, const float* __restrict__ bes,
                             const float* __restrict__ Wev, int Nn) {
    int idx = blockIdx.x * blockDim.x + threadIdx.x;
    if (idx >= Nn * F) return;
    int n = idx / F, f = idx & (F - 1);
    float xs[5];
#pragma unroll
    for (int i = 0; i < 5; i++) xs[i] = x[n * 5 + i];
    float as = bes[f], av = 0.f;
#pragma unroll
    for (int i = 0; i < 5; i++) { as += xs[i] * Wes[i * F + f]; av += xs[i] * Wev[i * F + f]; }
    float px = pos[n * 3], py = pos[n * 3 + 1], pz = pos[n * 3 + 2];
    d_sv[idx] = make_float4(as, av * px, av * py, av * pz);
}

// ---------------- in-degree over dst ----------------
__global__ void degree_kernel(const int* __restrict__ ei, int E) {
    int e = blockIdx.x * blockDim.x + threadIdx.x;
    if (e < E) atomicAdd(&d_cnt[ei[E + e]], 1.f);
}

// ---------------- fused edge MLP + message + scatter (per layer) ----------------
// Warp-per-8-edges, lane = feature f. f32x2 packed FMAs in GEMM2.
__global__ void __launch_bounds__(256) msg_kernel(
    const float* __restrict__ pos, const int* __restrict__ ei,
    const float* __restrict__ ea,
    const float* __restrict__ W1, const float* __restrict__ b1,
    const float* __restrict__ W2, const float* __restrict__ b2, int E) {
    __shared__ float sW1[5 * H];
    __shared__ float sb1[H];
    __shared__ float sW2[H * 3 * F];
    __shared__ float sb2[3 * F];
    __shared__ float sEIn[TILE * 5];
    __shared__ float sU[TILE * 3];
    __shared__ float h1T[H * TILE];    // [k][e]
    __shared__ int sSrc[TILE];
    __shared__ int sDst[TILE];

    int tid = threadIdx.x;
    for (int i = tid; i < 5 * H; i += 256) sW1[i] = W1[i];
    if (tid < H) sb1[tid] = b1[tid];
    for (int i = tid; i < H * 3 * F; i += 256) sW2[i] = W2[i];
    if (tid < 3 * F) sb2[tid] = b2[tid];

    int w = tid >> 5;       // warp 0..7
    int f = tid & 31;       // lane = feature
    int eBase = w * 8;      // warp owns 8 edges

    int ntiles = (E + TILE - 1) / TILE;
    for (int t = blockIdx.x; t < ntiles; t += gridDim.x) {
        int e0 = t * TILE;
        __syncthreads();  // protect shared reuse + weight-load visibility
        if (tid < TILE) {
            int e = e0 + tid;
            if (e < E) {
                int sn = ei[e], dn = ei[E + e];
                sSrc[tid] = sn; sDst[tid] = dn;
                float dx = pos[dn * 3 + 0] - pos[sn * 3 + 0];
                float dy = pos[dn * 3 + 1] - pos[sn * 3 + 1];
                float dz = pos[dn * 3 + 2] - pos[sn * 3 + 2];
                float dist = sqrtf(dx * dx + dy * dy + dz * dz + EPSF);
                float4 eav = *(const float4*)&ea[e * 4];
                sEIn[tid * 5 + 0] = dist;
                sEIn[tid * 5 + 1] = eav.x;
                sEIn[tid * 5 + 2] = eav.y;
                sEIn[tid * 5 + 3] = eav.z;
                sEIn[tid * 5 + 4] = eav.w;
                float inv = 1.f / dist;
                sU[tid * 3 + 0] = dx * inv;
                sU[tid * 3 + 1] = dy * inv;
                sU[tid * 3 + 2] = dz * inv;
            } else {
                sSrc[tid] = 0; sDst[tid] = 0;
#pragma unroll
                for (int i = 0; i < 5; i++) sEIn[tid * 5 + i] = 0.f;
#pragma unroll
                for (int i = 0; i < 3; i++) sU[tid * 3 + i] = 0.f;
            }
        }
        __syncthreads();

        // GEMM1: h1T[c][e] = elu(b1[c] + edge_in[e] . W1[:,c])
        {
            int e = tid & (TILE - 1);
            int ch = tid >> 6;  // 0..3 -> 16 cols each
            float ein[5];
#pragma unroll
            for (int i = 0; i < 5; i++) ein[i] = sEIn[e * 5 + i];
#pragma unroll
            for (int cc = 0; cc < 16; cc++) {
                int c = ch * 16 + cc;
                float a = sb1[c];
#pragma unroll
                for (int i = 0; i < 5; i++) a += ein[i] * sW1[i * H + c];
                // fast elu (exp path) — absolute err ~1e-7, fine vs 1e-3 tol
                h1T[c * TILE + e] = a > 0.f ? a : (__expf(a) - 1.f);
            }
        }
        __syncthreads();

        // GEMM2 (64 -> 96): accumulators as f32x2 pairs of edges.
        // acc[p] holds edges (eBase+2p, eBase+2p+1) for this lane's feature f.
        unsigned long long aS[4], aV[4], aX[4];
        {
            unsigned long long bs, bv, bx;
            PACK2(bs, sb2[f]); PACK2(bv, sb2[F + f]); PACK2(bx, sb2[2 * F + f]);
#pragma unroll
            for (int p = 0; p < 4; p++) { aS[p] = bs; aV[p] = bv; aX[p] = bx; }
        }
#pragma unroll 4
        for (int k = 0; k < H; k++) {
            const float* hrow = &h1T[k * TILE + eBase];
            ulonglong2 hA = *(const ulonglong2*)(hrow);      // edges 0-3 as 2x f32x2
            ulonglong2 hB = *(const ulonglong2*)(hrow + 4);  // edges 4-7
            unsigned long long ws2, wv2, wx2;
            PACK2(ws2, sW2[k * 3 * F + f]);
            PACK2(wv2, sW2[k * 3 * F + F + f]);
            PACK2(wx2, sW2[k * 3 * F + 2 * F + f]);
            FMA2(aS[0], hA.x, ws2); FMA2(aS[1], hA.y, ws2);
            FMA2(aS[2], hB.x, ws2); FMA2(aS[3], hB.y, ws2);
            FMA2(aV[0], hA.x, wv2); FMA2(aV[1], hA.y, wv2);
            FMA2(aV[2], hB.x, wv2); FMA2(aV[3], hB.y, wv2);
            FMA2(aX[0], hA.x, wx2); FMA2(aX[1], hA.y, wx2);
            FMA2(aX[2], hB.x, wx2); FMA2(aX[3], hB.y, wx2);
        }

        // messages + scatter: per edge, lanes = f -> fully coalesced LDG.128 + RED.v4
#pragma unroll
        for (int p = 0; p < 4; p++) {
            unsigned int gsl, gsh, gvl, gvh, gxl, gxh;
            asm("mov.b64 {%0, %1}, %2;" : "=r"(gsl), "=r"(gsh) : "l"(aS[p]));
            asm("mov.b64 {%0, %1}, %2;" : "=r"(gvl), "=r"(gvh) : "l"(aV[p]));
            asm("mov.b64 {%0, %1}, %2;" : "=r"(gxl), "=r"(gxh) : "l"(aX[p]));
#pragma unroll
            for (int half = 0; half < 2; half++) {
                int e = eBase + p * 2 + half;
                if (e0 + e >= E) continue;
                float gs = __uint_as_float(half ? gsh : gsl);
                float gv = __uint_as_float(half ? gvh : gvl);
                float gx = __uint_as_float(half ? gxh : gxl);
                int sn = sSrc[e], dn = sDst[e];
                float ux = sU[e * 3], uy = sU[e * 3 + 1], uz = sU[e * 3 + 2];
                float4 sv = d_sv[sn * F + f];   // coalesced across lanes
                float c = gx * sv.x;
                red_add_v4(&d_acc[dn * F + f],  // coalesced across lanes
                           gs * sv.x,
                           gv * sv.y + c * ux,
                           gv * sv.z + c * uy,
                           gv * sv.w + c * uz);
            }
        }
    }
}

// ---------------- node update: s += elu(as@Ws); v += av@Wv ----------------
__global__ void __launch_bounds__(256) upd_kernel(const float* __restrict__ Ws,
                                                  const float* __restrict__ Wv, int Nn) {
    __shared__ float sWs[F * F], sWv[F * F];
    __shared__ float4 sA[8][F];
    int tid = threadIdx.x;
    for (int i = tid; i < F * F; i += 256) { sWs[i] = Ws[i]; sWv[i] = Wv[i]; }
    int ln = tid >> 5, f = tid & 31;
    int n = blockIdx.x * 8 + ln;
    bool ok = n < Nn;
    if (ok) {
        float inv = 1.f / fmaxf(d_cnt[n], 1.f);
        float4 a = d_acc[n * F + f];
        sA[ln][f] = make_float4(a.x * inv, a.y * inv, a.z * inv, a.w * inv);
        d_acc[n * F + f] = make_float4(0.f, 0.f, 0.f, 0.f);  // ready for next layer
    }
    __syncthreads();
    if (ok) {
        float a = 0, vx = 0, vy = 0, vz = 0;
#pragma unroll
        for (int g = 0; g < F; g++) {
            float w1 = sWs[g * F + f], w2 = sWv[g * F + f];
            float4 ag = sA[ln][g];
            a  += ag.x * w1;
            vx += ag.y * w2;
            vy += ag.z * w2;
            vz += ag.w * w2;
        }
        float4 cur = d_sv[n * F + f];
        cur.x += elu1(a);
        cur.y += vx;
        cur.z += vy;
        cur.w += vz;
        d_sv[n * F + f] = cur;
    }
}

// ---------------- graph node counts ----------------
__global__ void gcnt_kernel(const int* __restrict__ batch, int Nn) {
    int n = blockIdx.x * blockDim.x + threadIdx.x;
    if (n < Nn) atomicAdd(&d_gcnt[batch[n]], 1.f);
}

// ---------------- invariant map + graph-sum pooling ----------------
__global__ void __launch_bounds__(128) inv_kernel(const int* __restrict__ batch,
                                                  const float* __restrict__ Winv,
                                                  const float* __restrict__ binv, int Nn) {
    __shared__ float sW[2 * F * NINVC];  // 32KB
    __shared__ float sFeat[2 * F];
    int tid = threadIdx.x;
    for (int i = tid; i < 2 * F * NINVC; i += 128) sW[i] = Winv[i];
    float bj = binv[tid];
    int n0 = blockIdx.x * 32;
    for (int nn = 0; nn < 32; nn++) {
        int n = n0 + nn;
        if (n >= Nn) break;
        __syncthreads();
        if (tid < F) {
            float4 sv = d_sv[n * F + tid];
            sFeat[tid] = sv.x;
            sFeat[F + tid] = sqrtf(sv.y * sv.y + sv.z * sv.z + sv.w * sv.w + EPSF);
        }
        __syncthreads();
        float acc = bj;
#pragma unroll 8
        for (int i = 0; i < 2 * F; i++) acc += sFeat[i] * sW[i * NINVC + tid];
        atomicAdd(&d_xgsum[batch[n] * NINVC + tid], acc);
    }
}

// ---------------- mean pool finalize ----------------
__global__ void poolfin_kernel(int G) {
    int i = blockIdx.x * blockDim.x + threadIdx.x;
    if (i < G * NINVC) d_xg[i] = d_xgsum[i] / fmaxf(d_gcnt[i / NINVC], 1.f);
}

// ---------------- batchnorm column stats ----------------
__global__ void bnstats_kernel(int which, int G) {
    const float* z = which ? d_z1 : d_xg;
    float* mean = which ? d_m2 : d_m1;
    float* rstd = which ? d_r2 : d_r1;
    int j = blockIdx.x;
    __shared__ float sS[256], sQ[256];
    float s = 0.f, q = 0.f;
    for (int g = threadIdx.x; g < G; g += 256) {
        float val = z[g * NINVC + j];
        s += val; q += val * val;
    }
    sS[threadIdx.x] = s; sQ[threadIdx.x] = q;
    __syncthreads();
    for (int off = 128; off > 0; off >>= 1) {
        if (threadIdx.x < off) { sS[threadIdx.x] += sS[threadIdx.x + off]; sQ[threadIdx.x] += sQ[threadIdx.x + off]; }
        __syncthreads();
    }
    if (threadIdx.x == 0) {
        float m = sS[0] / (float)G;
        float var = sQ[0] / (float)G - m * m;
        mean[j] = m;
        rstd[j] = rsqrtf(var + 1e-5f);
    }
}

// ---------------- fc1 ----------------
__global__ void __launch_bounds__(128) fc1_kernel(const float* __restrict__ Wf1,
                                                  const float* __restrict__ bf1,
                                                  const float* __restrict__ g1,
                                                  const float* __restrict__ be1, int G) {
    __shared__ float sA[NINVC];
    int tid = threadIdx.x;
    float gj = g1[tid], bej = be1[tid], mj = d_m1[tid], rj = d_r1[tid], bfj = bf1[tid];
    int r0 = blockIdx.x * 16;
    for (int rr = 0; rr < 16; rr++) {
        int r = r0 + rr;
        if (r >= G) break;
        __syncthreads();
        float a = (d_xg[r * NINVC + tid] - mj) * rj * gj + bej;
        sA[tid] = elu1(a);
        __syncthreads();
        float acc = bfj;
#pragma unroll 8
        for (int i = 0; i < NINVC; i++) acc += sA[i] * Wf1[i * NINVC + tid];
        d_z1[r * NINVC + tid] = acc;
    }
}

// ---------------- fc2 ----------------
__global__ void fc2_kernel(const float* __restrict__ Wf2, const float* __restrict__ bf2,
                           const float* __restrict__ g2, const float* __restrict__ be2,
                           float* __restrict__ out, int G) {
    int warp = threadIdx.x >> 5, lane = threadIdx.x & 31;
    int r = blockIdx.x * 8 + warp;
    if (r >= G) return;
    float acc = 0.f;
    for (int j = lane; j < NINVC; j += 32) {
        float a = (d_z1[r * NINVC + j] - d_m2[j]) * d_r2[j] * g2[j] + be2[j];
        acc += elu1(a) * Wf2[j];
    }
#pragma unroll
    for (int off = 16; off > 0; off >>= 1) acc += __shfl_down_sync(0xffffffffu, acc, off);
    if (lane == 0) out[r] = acc + bf2[0];
}

// ---------------- launch ----------------
extern "C" void kernel_launch(void* const* d_in, const int* in_sizes, int n_in,
                              void* d_out, int out_size) {
    const float* x     = (const float*)d_in[0];
    const float* pos   = (const float*)d_in[1];
    const int*   ei    = (const int*)d_in[2];
    const float* ea    = (const float*)d_in[3];
    const int*   batch = (const int*)d_in[4];
    const float* Wes   = (const float*)d_in[5];
    const float* bes   = (const float*)d_in[6];
    const float* Wev   = (const float*)d_in[7];
    const float* W1    = (const float*)d_in[8];
    const float* b1    = (const float*)d_in[9];
    const float* W2    = (const float*)d_in[10];
    const float* b2    = (const float*)d_in[11];
    const float* Ws    = (const float*)d_in[12];
    const float* Wv    = (const float*)d_in[13];
    const float* Winv  = (const float*)d_in[14];
    const float* binv  = (const float*)d_in[15];
    const float* g1    = (const float*)d_in[16];
    const float* be1   = (const float*)d_in[17];
    const float* Wf1   = (const float*)d_in[18];
    const float* bf1   = (const float*)d_in[19];
    const float* g2    = (const float*)d_in[20];
    const float* be2   = (const float*)d_in[21];
    const float* Wf2   = (const float*)d_in[22];
    const float* bf2   = (const float*)d_in[23];

    int Nn = in_sizes[0] / 5;
    int E  = in_sizes[2] / 2;
    int G  = out_size;
    float* out = (float*)d_out;

    zero_kernel<<<2048, 256>>>();
    embed_kernel<<<(Nn * F + 255) / 256, 256>>>(x, pos, Wes, bes, Wev, Nn);
    degree_kernel<<<(E + 255) / 256, 256>>>(ei, E);

    for (int l = 0; l < 4; l++) {
        msg_kernel<<<1480, 256>>>(pos, ei, ea,
                                  W1 + l * 5 * H, b1 + l * H,
                                  W2 + l * H * 3 * F, b2 + l * 3 * F, E);
        upd_kernel<<<(Nn + 7) / 8, 256>>>(Ws + l * F * F, Wv + l * F * F, Nn);
    }

    gcnt_kernel<<<(Nn + 255) / 256, 256>>>(batch, Nn);
    inv_kernel<<<(Nn + 31) / 32, 128>>>(batch, Winv, binv, Nn);
    poolfin_kernel<<<(G * NINVC + 255) / 256, 256>>>(G);
    bnstats_kernel<<<NINVC, 256>>>(0, G);
    fc1_kernel<<<(G + 15) / 16, 128>>>(Wf1, bf1, g1, be1, G);
    bnstats_kernel<<<NINVC, 256>>>(1, G);
    fc2_kernel<<<(G + 7) / 8, 256>>>(Wf2, bf2, g2, be2, out, G);
}